// round 4
// baseline (speedup 1.0000x reference)
#include <cuda_runtime.h>

// Problem constants (WordEmbedding: B=4, S=1024, DIM=1024, VOCAB=32000, BIT_DIM=15)
#define BDIM    1024
#define VOCAB   32000
#define NBITS   15
#define NTOK    4096          // B*S = 4*1024

// Output layout (concatenated, float32):
//   id_emb   [4096,1024]   at offset 0
//   bit_emb  [4096,1024]   at offset 4194304
//   logit    [4096,32000]  at offset 8388608
//   logit_w  [4096,15]     at offset 139460608
#define OFF_BIT   4194304
#define OFF_LOGIT 8388608
#define OFF_LW    139460608

// ---------------------------------------------------------------------------
// Kernel 1: id gather + bit embedding. One block per token, 256 threads,
// each thread owns one float4 (DIM/4 = 256).
// ---------------------------------------------------------------------------
__global__ __launch_bounds__(256) void embed_kernel(
    const int* __restrict__ ids,
    const float* __restrict__ weight,      // [VOCAB, DIM]
    const float* __restrict__ wbit,        // [NBITS, DIM]
    float* __restrict__ out_id,            // [NTOK, DIM]
    float* __restrict__ out_bit)           // [NTOK, DIM]
{
    int t = blockIdx.x;
    int id = ids[t];
    id = min(max(id, 0), VOCAB - 1);

    int d = threadIdx.x;  // 0..255 -> float4 index

    // id embedding: row gather
    const float4* wrow = (const float4*)(weight + (size_t)id * BDIM);
    float4 w = wrow[d];
    ((float4*)(out_id + (size_t)t * BDIM))[d] = w;

    // bit embedding: sum_k sign_k * weight_bit[k]; MSB first (shift 14-k)
    float4 acc = make_float4(0.f, 0.f, 0.f, 0.f);
#pragma unroll
    for (int k = 0; k < NBITS; k++) {
        float sgn = ((id >> (NBITS - 1 - k)) & 1) ? 1.0f : -1.0f;
        float4 wb = ((const float4*)(wbit + (size_t)k * BDIM))[d];
        acc.x = fmaf(sgn, wb.x, acc.x);
        acc.y = fmaf(sgn, wb.y, acc.y);
        acc.z = fmaf(sgn, wb.z, acc.z);
        acc.w = fmaf(sgn, wb.w, acc.w);
    }
    ((float4*)(out_bit + (size_t)t * BDIM))[d] = acc;
}

// ---------------------------------------------------------------------------
// Kernel 2: logit GEMM.  C[m,n] = dot(A[m,:], W[n,:])
//   A = tensor [NTOK, DIM] (K contiguous), W = weight [VOCAB, DIM] (K contiguous)
// Tile: BM=128, BN=128, BK=8, 256 threads, 8x8 micro-tile per thread.
// ---------------------------------------------------------------------------
#define GBM 128
#define GBN 128
#define GBK 8
#define GTM 8
#define GTN 8

__global__ __launch_bounds__(256) void gemm_kernel(
    const float* __restrict__ A,   // [NTOK, DIM]
    const float* __restrict__ W,   // [VOCAB, DIM]
    float* __restrict__ C)         // [NTOK, VOCAB]
{
    __shared__ float As[GBK][GBM];
    __shared__ float Bs[GBK][GBN];

    const int bn = blockIdx.x;     // N tile (vocab)
    const int bm = blockIdx.y;     // M tile (tokens)
    const int tid = threadIdx.x;
    const int tx = tid & 15;       // N direction (16)
    const int ty = tid >> 4;       // M direction (16)

    const float* Aptr = A + (size_t)bm * GBM * BDIM;
    const float* Wptr = W + (size_t)bn * GBN * BDIM;

    // load mapping: 256 threads, each loads one float4 per tile per matrix.
    const int lr = tid >> 1;             // row 0..127
    const int lc = (tid & 1) * 4;        // k offset 0 or 4

    float acc[GTM][GTN];
#pragma unroll
    for (int i = 0; i < GTM; i++)
#pragma unroll
        for (int j = 0; j < GTN; j++) acc[i][j] = 0.f;

    for (int k0 = 0; k0 < BDIM; k0 += GBK) {
        float4 av = *(const float4*)(Aptr + (size_t)lr * BDIM + k0 + lc);
        float4 bv = *(const float4*)(Wptr + (size_t)lr * BDIM + k0 + lc);
        As[lc + 0][lr] = av.x; As[lc + 1][lr] = av.y;
        As[lc + 2][lr] = av.z; As[lc + 3][lr] = av.w;
        Bs[lc + 0][lr] = bv.x; Bs[lc + 1][lr] = bv.y;
        Bs[lc + 2][lr] = bv.z; Bs[lc + 3][lr] = bv.w;
        __syncthreads();

#pragma unroll
        for (int kk = 0; kk < GBK; kk++) {
            float4 a0 = *(const float4*)&As[kk][ty * GTM];
            float4 a1 = *(const float4*)&As[kk][ty * GTM + 4];
            float4 b0 = *(const float4*)&Bs[kk][tx * GTN];
            float4 b1 = *(const float4*)&Bs[kk][tx * GTN + 4];
            float ra[GTM] = {a0.x, a0.y, a0.z, a0.w, a1.x, a1.y, a1.z, a1.w};
            float rb[GTN] = {b0.x, b0.y, b0.z, b0.w, b1.x, b1.y, b1.z, b1.w};
#pragma unroll
            for (int i = 0; i < GTM; i++)
#pragma unroll
                for (int j = 0; j < GTN; j++)
                    acc[i][j] = fmaf(ra[i], rb[j], acc[i][j]);
        }
        __syncthreads();
    }

    float* Cp = C + (size_t)(bm * GBM) * VOCAB + (size_t)bn * GBN;
#pragma unroll
    for (int i = 0; i < GTM; i++) {
        float* crow = Cp + (size_t)(ty * GTM + i) * VOCAB + tx * GTN;
        *(float4*)(crow)     = make_float4(acc[i][0], acc[i][1], acc[i][2], acc[i][3]);
        *(float4*)(crow + 4) = make_float4(acc[i][4], acc[i][5], acc[i][6], acc[i][7]);
    }
}

// ---------------------------------------------------------------------------
// Kernel 3: softmax over vocab + projection onto vocab bit codes.
//   logit_w[row,k] = (2*S_k - Z)/Z,  S_k = sum_{v: bit(14-k) of v == 1} e_v
// One block (256 thr) per row. Two passes over the 32000-wide row.
// Quad trick: for v0 = 4*i (multiple of 4), bits >=2 are shared by the quad;
// bit1 set exactly for e2,e3; bit0 set exactly for e1,e3.
// ---------------------------------------------------------------------------
__device__ __forceinline__ float warpMax(float v) {
#pragma unroll
    for (int o = 16; o > 0; o >>= 1) v = fmaxf(v, __shfl_xor_sync(0xffffffffu, v, o));
    return v;
}
__device__ __forceinline__ float warpSum(float v) {
#pragma unroll
    for (int o = 16; o > 0; o >>= 1) v += __shfl_xor_sync(0xffffffffu, v, o);
    return v;
}

__global__ __launch_bounds__(256) void softmax_bits_kernel(
    const float* __restrict__ logit,   // [NTOK, VOCAB]
    float* __restrict__ out_lw)        // [NTOK, NBITS]
{
    const int row = blockIdx.x;
    const int tid = threadIdx.x;
    const float4* x4 = (const float4*)(logit + (size_t)row * VOCAB);
    const int NQ = VOCAB / 4;  // 8000

    // ---- pass 1: row max ----
    float m = -3.4e38f;
    for (int i = tid; i < NQ; i += 256) {
        float4 v = x4[i];
        m = fmaxf(m, fmaxf(fmaxf(v.x, v.y), fmaxf(v.z, v.w)));
    }
    __shared__ float smax[8];
    m = warpMax(m);
    if ((tid & 31) == 0) smax[tid >> 5] = m;
    __syncthreads();
    if (tid < 32) {
        float t = (tid < 8) ? smax[tid] : -3.4e38f;
        t = warpMax(t);
        if (tid == 0) smax[0] = t;
    }
    __syncthreads();
    const float bm = smax[0];

    // ---- pass 2: Z and S_k ----
    float acc[16];  // acc[0..14] = S_k (k MSB-first), acc[15] = Z
#pragma unroll
    for (int k = 0; k < 16; k++) acc[k] = 0.f;

    for (int i = tid; i < NQ; i += 256) {
        float4 v = x4[i];
        int v0 = i * 4;
        float e0 = __expf(v.x - bm);
        float e1 = __expf(v.y - bm);
        float e2 = __expf(v.z - bm);
        float e3 = __expf(v.w - bm);
        float s4 = (e0 + e1) + (e2 + e3);
        acc[15] += s4;
        acc[14] += e1 + e3;   // bit 0
        acc[13] += e2 + e3;   // bit 1
#pragma unroll
        for (int k = 0; k < 13; k++) {        // bits 14..2 -> k = 0..12
            if ((v0 >> (14 - k)) & 1) acc[k] += s4;
        }
    }

    __shared__ float sacc[16][8];
#pragma unroll
    for (int k = 0; k < 16; k++) {
        float v = warpSum(acc[k]);
        if ((tid & 31) == 0) sacc[k][tid >> 5] = v;
    }
    __syncthreads();
    __shared__ float tot[16];
    if (tid < 16) {
        float t = 0.f;
#pragma unroll
        for (int w = 0; w < 8; w++) t += sacc[tid][w];
        tot[tid] = t;
    }
    __syncthreads();
    if (tid < NBITS) {
        float z = tot[15];
        out_lw[(size_t)row * NBITS + tid] = (2.0f * tot[tid] - z) / z;
    }
}

// ---------------------------------------------------------------------------
// Launch
// ---------------------------------------------------------------------------
extern "C" void kernel_launch(void* const* d_in, const int* in_sizes, int n_in,
                              void* d_out, int out_size)
{
    const int*   ids    = (const int*)d_in[0];     // [4,1024] int32
    const float* tensor = (const float*)d_in[1];   // [4,1024,1024] f32
    const float* weight = (const float*)d_in[2];   // [32000,1024] f32
    const float* wbit   = (const float*)d_in[3];   // [15,1024] f32

    float* out       = (float*)d_out;
    float* out_id    = out;
    float* out_bit   = out + OFF_BIT;
    float* out_logit = out + OFF_LOGIT;
    float* out_lw    = out + OFF_LW;

    embed_kernel<<<NTOK, 256>>>(ids, weight, wbit, out_id, out_bit);

    dim3 gg(VOCAB / GBN, NTOK / GBM);   // (250, 32)
    gemm_kernel<<<gg, 256>>>(tensor, weight, out_logit);

    softmax_bits_kernel<<<NTOK, 256>>>(out_logit, out_lw);
}

// round 11
// speedup vs baseline: 2.3926x; 2.3926x over previous
#include <cuda_runtime.h>
#include <cstdint>

// Problem constants (WordEmbedding: B=4, S=1024, DIM=1024, VOCAB=32000, BIT_DIM=15)
#define BDIM    1024
#define VOCAB   32000
#define NBITS   15
#define NTOK    4096

// Output layout (concatenated, float32)
#define OFF_BIT   4194304
#define OFF_LOGIT 8388608
#define OFF_LW    139460608

// ===========================================================================
// Kernel 1: id gather + bit embedding (unchanged, ~21us)
// ===========================================================================
__global__ __launch_bounds__(256) void embed_kernel(
    const int* __restrict__ ids, const float* __restrict__ weight,
    const float* __restrict__ wbit, float* __restrict__ out_id,
    float* __restrict__ out_bit)
{
    int t = blockIdx.x;
    int id = ids[t];
    id = min(max(id, 0), VOCAB - 1);
    int d = threadIdx.x;

    float4 w = ((const float4*)(weight + (size_t)id * BDIM))[d];
    ((float4*)(out_id + (size_t)t * BDIM))[d] = w;

    float4 acc = make_float4(0.f, 0.f, 0.f, 0.f);
#pragma unroll
    for (int k = 0; k < NBITS; k++) {
        float sgn = ((id >> (NBITS - 1 - k)) & 1) ? 1.0f : -1.0f;
        float4 wb = ((const float4*)(wbit + (size_t)k * BDIM))[d];
        acc.x = fmaf(sgn, wb.x, acc.x);
        acc.y = fmaf(sgn, wb.y, acc.y);
        acc.z = fmaf(sgn, wb.z, acc.z);
        acc.w = fmaf(sgn, wb.w, acc.w);
    }
    ((float4*)(out_bit + (size_t)t * BDIM))[d] = acc;
}

// ===========================================================================
// Kernel 2: 3xTF32 mma.sync GEMM (fp32-accurate via hi/lo split).
//   C[m,n] = dot(A[m,:], W[n,:]).
//   a = a_hi + a_lo (rna tf32 split, exact residual); accumulate
//   a_hi*b_hi + a_hi*b_lo + a_lo*b_hi on tensor pipe (lo*lo ~2^-22 dropped).
//   BM=128, BN=128, BK=32, 3-stage cp.async pipeline, 256 threads.
//   Warp grid 2(m) x 4(n): warp tile 64x32 -> 4x4 m16n8k8 fragments.
//   Smem rows padded to 36 floats: fragment LDS is exactly conflict-free.
// ===========================================================================
#define GBM 128
#define GBN 128
#define GBK 32
#define KCHUNKS (BDIM / GBK)           // 32
#define STAGES 3
#define SROW 36                         // floats per smem row (32 + 4 pad)
#define TILE_FLOATS (128 * SROW)
#define STAGE_FLOATS (2 * TILE_FLOATS)
#define GEMM_SMEM (STAGES * STAGE_FLOATS * 4)   // 110592 bytes

__device__ __forceinline__ uint32_t smem_u32(const void* p) {
    uint32_t a;
    asm("{ .reg .u64 t; cvta.to.shared.u64 t, %1; cvt.u32.u64 %0, t; }" : "=r"(a) : "l"(p));
    return a;
}
__device__ __forceinline__ void cp_async16(uint32_t saddr, const void* gptr) {
    asm volatile("cp.async.cg.shared.global [%0], [%1], 16;" :: "r"(saddr), "l"(gptr));
}
__device__ __forceinline__ void cp_commit() {
    asm volatile("cp.async.commit_group;" ::: "memory");
}
template <int N>
__device__ __forceinline__ void cp_wait() {
    asm volatile("cp.async.wait_group %0;" :: "n"(N) : "memory");
}
__device__ __forceinline__ uint32_t f2tf32(float f) {
    uint32_t r;
    asm("cvt.rna.tf32.f32 %0, %1;" : "=r"(r) : "f"(f));
    return r;
}
// split x into hi (tf32) and lo (tf32 of exact residual)
__device__ __forceinline__ void tf32_split(float x, uint32_t& hi, uint32_t& lo) {
    hi = f2tf32(x);
    lo = f2tf32(x - __uint_as_float(hi));
}
__device__ __forceinline__ void mma_tf32(float c[4], const uint32_t a[4],
                                         uint32_t b0, uint32_t b1) {
    asm volatile(
        "mma.sync.aligned.m16n8k8.row.col.f32.tf32.tf32.f32 "
        "{%0,%1,%2,%3}, {%4,%5,%6,%7}, {%8,%9}, {%0,%1,%2,%3};"
        : "+f"(c[0]), "+f"(c[1]), "+f"(c[2]), "+f"(c[3])
        : "r"(a[0]), "r"(a[1]), "r"(a[2]), "r"(a[3]), "r"(b0), "r"(b1));
}

__global__ __launch_bounds__(256, 1) void gemm_mma_kernel(
    const float* __restrict__ A,   // [NTOK, BDIM]
    const float* __restrict__ W,   // [VOCAB, BDIM]
    float* __restrict__ C)         // [NTOK, VOCAB]
{
    extern __shared__ float smem[];
    const uint32_t sbase = smem_u32(smem);
    const int tid = threadIdx.x;
    const int wid = tid >> 5;
    const int lane = tid & 31;
    const int wm = wid & 1;        // M direction (2)
    const int wn = wid >> 1;       // N direction (4)
    const int bm = blockIdx.x;     // fast -> shares B tile in L2
    const int bn = blockIdx.y;

    const float* Abase = A + (size_t)bm * GBM * BDIM;
    const float* Bbase = W + (size_t)bn * GBN * BDIM;

    auto load_stage = [&](int ch, int buf) {
        const int k0 = ch * GBK;
        const uint32_t sA = sbase + (uint32_t)buf * STAGE_FLOATS * 4;
        const uint32_t sB = sA + TILE_FLOATS * 4;
#pragma unroll
        for (int i = 0; i < 4; i++) {
            int idx = tid + i * 256;
            int r = idx >> 3, c4 = idx & 7;
            cp_async16(sA + (uint32_t)(r * SROW + c4 * 4) * 4,
                       Abase + (size_t)r * BDIM + k0 + c4 * 4);
        }
#pragma unroll
        for (int i = 0; i < 4; i++) {
            int idx = tid + i * 256;
            int r = idx >> 3, c4 = idx & 7;
            cp_async16(sB + (uint32_t)(r * SROW + c4 * 4) * 4,
                       Bbase + (size_t)r * BDIM + k0 + c4 * 4);
        }
        cp_commit();
    };

    float acc[4][4][4];
#pragma unroll
    for (int mi = 0; mi < 4; mi++)
#pragma unroll
        for (int ni = 0; ni < 4; ni++)
#pragma unroll
            for (int j = 0; j < 4; j++) acc[mi][ni][j] = 0.f;

    load_stage(0, 0);
    load_stage(1, 1);

    const int g = lane >> 2;   // 0..7
    const int t = lane & 3;    // 0..3

    for (int ch = 0; ch < KCHUNKS; ch++) {
        cp_wait<STAGES - 2>();
        __syncthreads();

        const int buf = ch % STAGES;
        const float* sA = smem + buf * STAGE_FLOATS;
        const float* sB = sA + TILE_FLOATS;
        const float* sAw = sA + (wm * 64 + g) * SROW;
        const float* sBw = sB + (wn * 32 + g) * SROW;

#pragma unroll
        for (int kk = 0; kk < GBK / 8; kk++) {
            const int kb = kk * 8 + t;
            uint32_t ah[4][4], al[4][4], bh[4][2], bl[4][2];
#pragma unroll
            for (int mi = 0; mi < 4; mi++) {
                const float* p = sAw + mi * 16 * SROW;
                tf32_split(p[kb],            ah[mi][0], al[mi][0]);
                tf32_split(p[8 * SROW + kb], ah[mi][1], al[mi][1]);
                tf32_split(p[kb + 4],        ah[mi][2], al[mi][2]);
                tf32_split(p[8 * SROW + kb + 4], ah[mi][3], al[mi][3]);
            }
#pragma unroll
            for (int ni = 0; ni < 4; ni++) {
                const float* p = sBw + ni * 8 * SROW;
                tf32_split(p[kb],     bh[ni][0], bl[ni][0]);
                tf32_split(p[kb + 4], bh[ni][1], bl[ni][1]);
            }
#pragma unroll
            for (int mi = 0; mi < 4; mi++)
#pragma unroll
                for (int ni = 0; ni < 4; ni++) {
                    // small cross terms first, then hi*hi
                    mma_tf32(acc[mi][ni], al[mi], bh[ni][0], bh[ni][1]);
                    mma_tf32(acc[mi][ni], ah[mi], bl[ni][0], bl[ni][1]);
                    mma_tf32(acc[mi][ni], ah[mi], bh[ni][0], bh[ni][1]);
                }
        }

        __syncthreads();
        if (ch + STAGES - 1 < KCHUNKS)
            load_stage(ch + STAGES - 1, (ch + STAGES - 1) % STAGES);
        else
            cp_commit();   // keep wait_group accounting consistent
    }

    // epilogue: c0,c1 at (row g, col 2t), c2,c3 at (row g+8, col 2t)
    float* Cw = C + (size_t)(bm * GBM + wm * 64) * VOCAB + (size_t)bn * GBN + wn * 32;
#pragma unroll
    for (int mi = 0; mi < 4; mi++) {
        float* r0 = Cw + (size_t)(mi * 16 + g) * VOCAB + 2 * t;
        float* r1 = r0 + 8 * (size_t)VOCAB;
#pragma unroll
        for (int ni = 0; ni < 4; ni++) {
            *(float2*)(r0 + ni * 8) = make_float2(acc[mi][ni][0], acc[mi][ni][1]);
            *(float2*)(r1 + ni * 8) = make_float2(acc[mi][ni][2], acc[mi][ni][3]);
        }
    }
}

// ===========================================================================
// Kernel 3: softmax over vocab + projection onto vocab bit codes (unchanged)
// ===========================================================================
__device__ __forceinline__ float warpMax(float v) {
#pragma unroll
    for (int o = 16; o > 0; o >>= 1) v = fmaxf(v, __shfl_xor_sync(0xffffffffu, v, o));
    return v;
}
__device__ __forceinline__ float warpSum(float v) {
#pragma unroll
    for (int o = 16; o > 0; o >>= 1) v += __shfl_xor_sync(0xffffffffu, v, o);
    return v;
}

__global__ __launch_bounds__(256) void softmax_bits_kernel(
    const float* __restrict__ logit, float* __restrict__ out_lw)
{
    const int row = blockIdx.x;
    const int tid = threadIdx.x;
    const float4* x4 = (const float4*)(logit + (size_t)row * VOCAB);
    const int NQ = VOCAB / 4;

    float m = -3.4e38f;
    for (int i = tid; i < NQ; i += 256) {
        float4 v = x4[i];
        m = fmaxf(m, fmaxf(fmaxf(v.x, v.y), fmaxf(v.z, v.w)));
    }
    __shared__ float smax[8];
    m = warpMax(m);
    if ((tid & 31) == 0) smax[tid >> 5] = m;
    __syncthreads();
    if (tid < 32) {
        float t = (tid < 8) ? smax[tid] : -3.4e38f;
        t = warpMax(t);
        if (tid == 0) smax[0] = t;
    }
    __syncthreads();
    const float bmv = smax[0];

    float acc[16];
#pragma unroll
    for (int k = 0; k < 16; k++) acc[k] = 0.f;

    for (int i = tid; i < NQ; i += 256) {
        float4 v = x4[i];
        int v0 = i * 4;
        float e0 = __expf(v.x - bmv);
        float e1 = __expf(v.y - bmv);
        float e2 = __expf(v.z - bmv);
        float e3 = __expf(v.w - bmv);
        float s4 = (e0 + e1) + (e2 + e3);
        acc[15] += s4;
        acc[14] += e1 + e3;
        acc[13] += e2 + e3;
#pragma unroll
        for (int k = 0; k < 13; k++) {
            if ((v0 >> (14 - k)) & 1) acc[k] += s4;
        }
    }

    __shared__ float sacc[16][8];
#pragma unroll
    for (int k = 0; k < 16; k++) {
        float v = warpSum(acc[k]);
        if ((tid & 31) == 0) sacc[k][tid >> 5] = v;
    }
    __syncthreads();
    __shared__ float tot[16];
    if (tid < 16) {
        float t = 0.f;
#pragma unroll
        for (int w = 0; w < 8; w++) t += sacc[tid][w];
        tot[tid] = t;
    }
    __syncthreads();
    if (tid < NBITS) {
        float z = tot[15];
        out_lw[(size_t)row * NBITS + tid] = (2.0f * tot[tid] - z) / z;
    }
}

// ===========================================================================
// Launch
// ===========================================================================
extern "C" void kernel_launch(void* const* d_in, const int* in_sizes, int n_in,
                              void* d_out, int out_size)
{
    const int*   ids    = (const int*)d_in[0];
    const float* tensor = (const float*)d_in[1];
    const float* weight = (const float*)d_in[2];
    const float* wbit   = (const float*)d_in[3];

    float* out       = (float*)d_out;
    float* out_id    = out;
    float* out_bit   = out + OFF_BIT;
    float* out_logit = out + OFF_LOGIT;
    float* out_lw    = out + OFF_LW;

    static bool attr_set = false;
    if (!attr_set) {
        cudaFuncSetAttribute(gemm_mma_kernel,
                             cudaFuncAttributeMaxDynamicSharedMemorySize, GEMM_SMEM);
        attr_set = true;
    }

    embed_kernel<<<NTOK, 256>>>(ids, weight, wbit, out_id, out_bit);

    dim3 gg(NTOK / GBM, VOCAB / GBN);   // (32, 250); x fast -> B-tile L2 reuse
    gemm_mma_kernel<<<gg, 256, GEMM_SMEM>>>(tensor, weight, out_logit);

    softmax_bits_kernel<<<NTOK, 256>>>(out_logit, out_lw);
}